// round 15
// baseline (speedup 1.0000x reference)
#include <cuda_runtime.h>
#include <cuda_bf16.h>
#include <math_constants.h>
#include <cstdint>

#define DD 128
#define BQ 32
#define KTOP 16
#define TILE_R 64
#define TPB 256
#define NCTA 444
#define SCST 34

// smem byte offsets (per CTA, ~38.6 KB -> 3 CTAs/SM)
#define SM_AHI  0              // 64 rows x 256B bf16 (16 KB); fp32 scratch in setup
#define SM_QHI  16384          // 32 rows x 256B bf16 (8 KB)
#define SM_SC   24576          // 64*34*4 = 8704
#define SM_MN   33280          // 64 floats
#define SM_RW   33536          // 64 floats
#define SM_W    33792          // 64 floats
#define SM_CB   34048          // 32 floats
#define SM_TH   34176          // 32 floats
#define SM_FLG  34304          // 32 ints
#define SM_HV   34432          // 32*16 floats
#define SM_HX   36480          // 32*16 ints
#define SMEM_BYTES 38528

__device__ float g_q[BQ*DD];
__device__ float g_qn[BQ];
__device__ float g_cand_s[NCTA*BQ*KTOP];
__device__ int   g_cand_i[NCTA*BQ*KTOP];
__device__ float g_minred[NCTA*BQ];

// ---------------- helpers ----------------
__device__ __forceinline__ uint32_t smem_u32(const void* p) {
    uint32_t a;
    asm("{ .reg .u64 t; cvta.to.shared.u64 t, %1; cvt.u32.u64 %0, t; }" : "=r"(a) : "l"(p));
    return a;
}
__device__ __forceinline__ uint32_t pack_bf16x2(float hi_elem, float lo_elem) {
    uint32_t r;
    asm("cvt.rn.bf16x2.f32 %0, %1, %2;" : "=r"(r) : "f"(hi_elem), "f"(lo_elem));
    return r;
}
__device__ __forceinline__ float rsqrt_nr(float x) {
    float r;
    asm("rsqrt.approx.f32 %0, %1;" : "=f"(r) : "f"(x));
    r = r * fmaf(-0.5f * x * r, r, 1.5f);
    return r;
}
__device__ __forceinline__ void ldsm_x4(uint32_t& r0, uint32_t& r1, uint32_t& r2, uint32_t& r3, uint32_t a) {
    asm volatile("ldmatrix.sync.aligned.m8n8.x4.shared.b16 {%0,%1,%2,%3}, [%4];"
                 : "=r"(r0), "=r"(r1), "=r"(r2), "=r"(r3) : "r"(a));
}
__device__ __forceinline__ void ldsm_x2(uint32_t& r0, uint32_t& r1, uint32_t a) {
    asm volatile("ldmatrix.sync.aligned.m8n8.x2.shared.b16 {%0,%1}, [%2];"
                 : "=r"(r0), "=r"(r1) : "r"(a));
}
__device__ __forceinline__ void mma16816(float* c, uint32_t a0, uint32_t a1, uint32_t a2, uint32_t a3,
                                         uint32_t b0, uint32_t b1) {
    asm volatile("mma.sync.aligned.m16n8k16.row.col.f32.bf16.bf16.f32 "
                 "{%0,%1,%2,%3}, {%4,%5,%6,%7}, {%8,%9}, {%0,%1,%2,%3};"
                 : "+f"(c[0]), "+f"(c[1]), "+f"(c[2]), "+f"(c[3])
                 : "r"(a0), "r"(a1), "r"(a2), "r"(a3), "r"(b0), "r"(b1));
}

// ---------------------------------------------------------------------------
// k_main: register-staged bf16 HMMA dots (64-row tiles, 3 CTAs/SM)
// ---------------------------------------------------------------------------
__global__ void __launch_bounds__(TPB, 3)
k_main(const float* __restrict__ query, const float* __restrict__ mem,
       const float* __restrict__ imp, const int* __restrict__ ts,
       const float* __restrict__ Wq, const float* __restrict__ bqv,
       const int* __restrict__ ctp, int N, int tpc) {
    extern __shared__ char smem[];
    const uint32_t sb = smem_u32(smem);
    float* sSC  = (float*)(smem + SM_SC);
    float* sMN  = (float*)(smem + SM_MN);
    float* sRW  = (float*)(smem + SM_RW);
    float* sW   = (float*)(smem + SM_W);
    float* sCB  = (float*)(smem + SM_CB);
    float* sTH  = (float*)(smem + SM_TH);
    int*   sFLG = (int*)(smem + SM_FLG);
    float* sHV  = (float*)(smem + SM_HV);
    int*   sHX  = (int*)(smem + SM_HX);

    const int t    = threadIdx.x;
    const int wid  = t >> 5;
    const int lane = t & 31;
    const int cta  = blockIdx.x;

    // ===== setup: exact q = query @ Wq^T + bq; Qhi bf16 operand =====
    {
        float* sQF = (float*)(smem + SM_AHI);   // fp32 scratch (16 KB)
        for (int o = t; o < BQ*DD; o += TPB) {
            int b = o >> 7, j = o & 127;
            const float4* wr = (const float4*)(Wq + (size_t)j * DD);
            const float4* qr = (const float4*)(query + (size_t)b * DD);
            float a0 = 0.f, a1 = 0.f, a2 = 0.f, a3 = 0.f;
            #pragma unroll 8
            for (int dd = 0; dd < 32; dd++) {
                float4 wv = wr[dd]; float4 qv = qr[dd];
                a0 = fmaf(qv.x, wv.x, a0); a1 = fmaf(qv.y, wv.y, a1);
                a2 = fmaf(qv.z, wv.z, a2); a3 = fmaf(qv.w, wv.w, a3);
            }
            float v = ((a0 + a1) + (a2 + a3)) + bqv[j];
            sQF[o] = v;
            g_q[o] = v;
        }
        __syncthreads();
        if (t < BQ) {
            float s = 0.f;
            for (int jj = 0; jj < DD; jj++) {
                int j = (jj + 5*t) & 127;
                float v = sQF[t*DD + j];
                s = fmaf(v, v, s);
            }
            float qn = sqrtf(s);
            g_qn[t] = qn;
            sCB[t] = 0.7f / qn;
            sTH[t] = -CUDART_INF_F;
            sFLG[t] = 0;
        }
        for (int o = t; o < BQ*KTOP; o += TPB) { sHV[o] = -CUDART_INF_F; sHX[o] = 0x7fffffff; }
        __syncthreads();   // sQF fully read below before AHI reuse? QHI pack reads sQF:
        for (int o = t; o < BQ*DD; o += TPB) {
            int b = o >> 7, j = o & 127;
            *(__nv_bfloat16*)(smem + SM_QHI + b*256 + (((j >> 3) ^ (b & 7)) << 4) + (j & 7)*2)
                = __float2bfloat16(sQF[o]);
        }
        __syncthreads();   // QHI ready; AHI region free for per-tile reuse
    }

    const float inv_ct1 = 1.0f / ((float)(*ctp) + 1.0f);

    float lmn[4];
    #pragma unroll
    for (int j = 0; j < 4; j++) lmn[j] = CUDART_INF_F;

    const long tile0 = (long)cta * tpc;

    // assignments
    const int p    = wid & 3;            // mma slab id
    const int qhf  = wid >> 2;           // mma query half
    const int rsl  = p * 16;
    const int rA   = rsl + (lane & 15);
    const uint32_t aBase = sb + SM_AHI + rA * 256;
    const int aSel = lane >> 4;
    const int qB   = lane & 7;
    const int bSel = (lane >> 3) & 1;
    const int gid  = lane >> 2;
    const int tig  = lane & 3;
    // convert: warp w owns rows wid*8 .. wid*8+7; lane l = chunk l (16B)
    const int r0l  = wid * 8;
    // AHI store address for lane l, row r: r*256 + (((l>>1)^(r&7))<<4) + (l&1)*8
    const uint32_t stoff = (uint32_t)((lane & 1) * 8);

    for (int it = 0; it < tpc; it++) {
        int base = (int)((tile0 + it) * TILE_R);
        if (base >= N) break;
        const bool fulli = (base + TILE_R <= N);

        // ---- load 8 rows directly to registers (coalesced: 1 row / LDG.128) ----
        float4 v[8];
        {
            const float4* g0 = (const float4*)(mem + (size_t)(base + r0l) * DD) + lane;
            if (fulli) {
                #pragma unroll
                for (int j = 0; j < 8; j++) v[j] = g0[j * 32];
            } else {
                #pragma unroll
                for (int j = 0; j < 8; j++) {
                    v[j] = make_float4(0.f, 0.f, 0.f, 0.f);
                    if (base + r0l + j < N) v[j] = g0[j * 32];
                }
            }
        }
        // per-row scalars for own rows (overlaps row-LDG latency)
        if (lane < 8) {
            int r = r0l + lane;
            int row = base + r;
            if (row < N) {
                sRW[r] = 0.3f * ((float)ts[row] + 1.0f) * inv_ct1;
                sW[r]  = fmaf(0.5f, imp[row], 0.5f);
            } else { sRW[r] = 0.f; sW[r] = 0.f; }
        }

        // ---- norms (warp shfl reduce) + bf16 convert + swizzled STS.64 ----
        #pragma unroll
        for (int j = 0; j < 8; j++) {
            int r = r0l + j;
            float s = v[j].x*v[j].x + v[j].y*v[j].y + v[j].z*v[j].z + v[j].w*v[j].w;
            #pragma unroll
            for (int off = 16; off > 0; off >>= 1)
                s += __shfl_xor_sync(0xffffffffu, s, off);
            if (lane == 0) sMN[r] = s;
            uint2 w2;
            w2.x = pack_bf16x2(v[j].y, v[j].x);
            w2.y = pack_bf16x2(v[j].w, v[j].z);
            uint32_t addr = sb + SM_AHI + (uint32_t)(r * 256)
                          + (uint32_t)((((lane >> 1) ^ (r & 7)) << 4)) + stoff;
            asm volatile("st.shared.v2.u32 [%0], {%1, %2};" :: "r"(addr), "r"(w2.x), "r"(w2.y) : "memory");
        }
        __syncthreads();   // AHI + norms + scalars ready

        // ---- HMMA: 16-row slab x 16-query half, K=128 ----
        float C[2][4];
        #pragma unroll
        for (int nt = 0; nt < 2; nt++)
            #pragma unroll
            for (int i = 0; i < 4; i++) C[nt][i] = 0.f;

        const uint32_t qb0 = sb + SM_QHI + (qhf*16 + 0*8 + qB)*256;
        const uint32_t qb1 = sb + SM_QHI + (qhf*16 + 1*8 + qB)*256;
        #pragma unroll
        for (int ks = 0; ks < 8; ks++) {
            uint32_t a0, a1, a2, a3;
            ldsm_x4(a0, a1, a2, a3, aBase + (((2*ks + aSel) ^ (rA & 7)) << 4));
            uint32_t swz = ((2*ks + bSel) ^ qB) << 4;
            uint32_t b0, b1;
            ldsm_x2(b0, b1, qb0 + swz); mma16816(C[0], a0, a1, a2, a3, b0, b1);
            ldsm_x2(b0, b1, qb1 + swz); mma16816(C[1], a0, a1, a2, a3, b0, b1);
        }

        // ---- epilogue: scores + min-d2 + in-register flag reduction ----
        {
            int rla = rsl + gid, rlb = rla + 8;
            bool va = (base + rla < N), vb = (base + rlb < N);
            float mnA = sMN[rla], mnB = sMN[rlb];
            float invA = va ? rsqrt_nr(mnA) : 0.f;
            float invB = vb ? rsqrt_nr(mnB) : 0.f;
            float recA = sRW[rla], wA = sW[rla];
            float recB = sRW[rlb], wB = sW[rlb];
            #pragma unroll
            for (int nt = 0; nt < 2; nt++) {
                int q0 = qhf*16 + nt*8 + tig*2;
                float cb0 = sCB[q0], cb1 = sCB[q0+1];
                float dA0 = C[nt][0], dA1 = C[nt][1];
                float dB0 = C[nt][2], dB1 = C[nt][3];
                float2 sa, sbv;
                sa.x  = va ? fmaf(dA0*invA, cb0, recA) * wA : -CUDART_INF_F;
                sa.y  = va ? fmaf(dA1*invA, cb1, recA) * wA : -CUDART_INF_F;
                sbv.x = vb ? fmaf(dB0*invB, cb0, recB) * wB : -CUDART_INF_F;
                sbv.y = vb ? fmaf(dB1*invB, cb1, recB) * wB : -CUDART_INF_F;
                *(float2*)(sSC + rla*SCST + q0) = sa;
                *(float2*)(sSC + rlb*SCST + q0) = sbv;
                float m0 = CUDART_INF_F, m1 = CUDART_INF_F;
                if (va) { m0 = fmaf(-2.f, dA0, mnA); m1 = fmaf(-2.f, dA1, mnA); }
                if (vb) { m0 = fminf(m0, fmaf(-2.f, dB0, mnB)); m1 = fminf(m1, fmaf(-2.f, dB1, mnB)); }
                lmn[nt*2]   = fminf(lmn[nt*2],   m0);
                lmn[nt*2+1] = fminf(lmn[nt*2+1], m1);
                float mq0 = fmaxf(sa.x, sbv.x);
                float mq1 = fmaxf(sa.y, sbv.y);
                #pragma unroll
                for (int off = 4; off < 32; off <<= 1) {
                    mq0 = fmaxf(mq0, __shfl_xor_sync(0xffffffffu, mq0, off));
                    mq1 = fmaxf(mq1, __shfl_xor_sync(0xffffffffu, mq1, off));
                }
                if (gid == 0) {
                    if (mq0 > sTH[q0])   sFLG[q0]   = 1;
                    if (mq1 > sTH[q0+1]) sFLG[q0+1] = 1;
                }
            }
        }
        __syncthreads();

        // ---- phase B: full 64-row scan only when flagged ----
        if (t < BQ && sFLG[t]) {
            sFLG[t] = 0;
            float th = sTH[t];
            float* hv = sHV + t*KTOP;
            int*   hx = sHX + t*KTOP;
            for (int e = 0; e < TILE_R; e += 4) {
                float v0 = sSC[(e+0)*SCST + t];
                float v1 = sSC[(e+1)*SCST + t];
                float v2 = sSC[(e+2)*SCST + t];
                float v3 = sSC[(e+3)*SCST + t];
                float mx = fmaxf(fmaxf(v0, v1), fmaxf(v2, v3));
                if (mx > th) {
                    #pragma unroll
                    for (int u = 0; u < 4; u++) {
                        float sc = (u==0)?v0:(u==1)?v1:(u==2)?v2:v3;
                        if (sc > th) {
                            int idx = base + e + u;
                            int pos = KTOP - 1;
                            #pragma unroll
                            for (int s = KTOP - 1; s > 0; s--)
                                if (sc > hv[s-1]) { hv[s] = hv[s-1]; hx[s] = hx[s-1]; pos = s-1; }
                            hv[pos] = sc; hx[pos] = idx;
                            th = hv[KTOP-1];
                        }
                    }
                }
            }
            sTH[t] = th;
        }
        // no barrier: next iter's pre-MMA __syncthreads orders phase B vs sSC reuse
    }
    __syncthreads();

    // ---- reduce lmn: q = qhf*16 + nt*8 + tig*2 + pp; 32 contributors/q ----
    #pragma unroll
    for (int nt = 0; nt < 2; nt++)
        #pragma unroll
        for (int pp = 0; pp < 2; pp++) {
            int q = qhf*16 + nt*8 + tig*2 + pp;
            sSC[q*32 + p*8 + gid] = lmn[nt*2+pp];
        }
    __syncthreads();
    if (t < BQ) {
        float mn = CUDART_INF_F;
        #pragma unroll 4
        for (int i = 0; i < 32; i++) mn = fminf(mn, sSC[t*32 + ((i + t) & 31)]);
        g_minred[cta*BQ + t] = mn;
        float* cs = g_cand_s + ((size_t)cta*BQ + t) * KTOP;
        int*   ci = g_cand_i + ((size_t)cta*BQ + t) * KTOP;
        #pragma unroll
        for (int j = 0; j < KTOP; j++) { cs[j] = sHV[t*KTOP + j]; ci[j] = sHX[t*KTOP + j]; }
    }
}

// ---------------------------------------------------------------------------
// k_topk: approx top-32 merge (dynamic smem), exact rescoring, exact top-16
// ---------------------------------------------------------------------------
#define MCAND (NCTA*KTOP)
#define TOPK_SMEM (MCAND*8)
__global__ void __launch_bounds__(256)
k_topk(const float* __restrict__ mem, const float* __restrict__ imp,
       const int* __restrict__ ts, const int* __restrict__ ctp,
       float* __restrict__ out) {
    extern __shared__ char dyn[];
    float* cs = (float*)dyn;
    int*   ci = (int*)(dyn + MCAND*4);
    __shared__ float rv[256];
    __shared__ int   ri[256], rp[256];
    __shared__ int   candI[32];
    __shared__ float exS[32];
    __shared__ int   exI[32];

    int q = blockIdx.x;
    int t = threadIdx.x;

    for (int i = t; i < MCAND; i += 256) {
        int c = i >> 4, j = i & (KTOP-1);
        size_t g = ((size_t)c*BQ + q) * KTOP + j;
        cs[i] = g_cand_s[g];
        ci[i] = g_cand_i[g];
    }
    __syncthreads();

    for (int pass = 0; pass < 32; pass++) {
        float bv = -CUDART_INF_F; int bi = 0x7fffffff, bp = 0;
        for (int i = t; i < MCAND; i += 256) {
            float v = cs[i]; int id = ci[i];
            if (v > bv || (v == bv && id < bi)) { bv = v; bi = id; bp = i; }
        }
        rv[t] = bv; ri[t] = bi; rp[t] = bp;
        __syncthreads();
        for (int s = 128; s > 0; s >>= 1) {
            if (t < s && (rv[t+s] > rv[t] || (rv[t+s] == rv[t] && ri[t+s] < ri[t]))) {
                rv[t] = rv[t+s]; ri[t] = ri[t+s]; rp[t] = rp[t+s];
            }
            __syncthreads();
        }
        if (t == 0) {
            candI[pass] = (rv[0] == -CUDART_INF_F) ? 0x7fffffff : ri[0];
            cs[rp[0]] = -CUDART_INF_F;
        }
        __syncthreads();
    }

    const float ctf1 = (float)(*ctp) + 1.0f;
    if (t < 32) {
        int idx = candI[t];
        float sc = -CUDART_INF_F;
        if (idx != 0x7fffffff) {
            const float4* mr = (const float4*)(mem + (size_t)idx * DD);
            const float4* qr = (const float4*)(g_q + q * DD);
            float dot = 0.f, mn2 = 0.f;
            #pragma unroll 8
            for (int c = 0; c < 32; c++) {
                float4 a = mr[c]; float4 b = qr[c];
                dot = fmaf(a.x, b.x, dot); dot = fmaf(a.y, b.y, dot);
                dot = fmaf(a.z, b.z, dot); dot = fmaf(a.w, b.w, dot);
                mn2 = fmaf(a.x, a.x, mn2); mn2 = fmaf(a.y, a.y, mn2);
                mn2 = fmaf(a.z, a.z, mn2); mn2 = fmaf(a.w, a.w, mn2);
            }
            float den = fmaxf(g_qn[q] * sqrtf(mn2), 1e-8f);
            float rec = ((float)ts[idx] + 1.0f) / ctf1;
            sc = (0.7f * dot / den + 0.3f * rec) * fmaf(0.5f, imp[idx], 0.5f);
        }
        exS[t] = sc; exI[t] = idx;
    }
    __syncthreads();

    if (t == 0) {
        for (int pass = 0; pass < KTOP; pass++) {
            float bv = -CUDART_INF_F; int bi = 0x7fffffff, bp = 0;
            for (int i = 0; i < 32; i++)
                if (exS[i] > bv || (exS[i] == bv && exI[i] < bi)) { bv = exS[i]; bi = exI[i]; bp = i; }
            out[q*KTOP + pass]           = bv;
            out[BQ*KTOP + q*KTOP + pass] = (float)bi;
            exS[bp] = -CUDART_INF_F;
        }
    }
}

// ---------------------------------------------------------------------------
__global__ void __launch_bounds__(256)
k_nov(float* __restrict__ out) {
    __shared__ float rv[256];
    int q = blockIdx.x, t = threadIdx.x;
    float m = CUDART_INF_F;
    for (int c = t; c < NCTA; c += 256) m = fminf(m, g_minred[c*BQ + q]);
    rv[t] = m;
    __syncthreads();
    for (int s = 128; s > 0; s >>= 1) {
        if (t < s) rv[t] = fminf(rv[t], rv[t+s]);
        __syncthreads();
    }
    if (t == 0) {
        float qn = g_qn[q];
        float dist = sqrtf(fmaxf(qn*qn + rv[0], 0.0f));
        out[2*BQ*KTOP + q] = fminf(1.0f, dist * 0.1f);
    }
}

// ---------------------------------------------------------------------------
extern "C" void kernel_launch(void* const* d_in, const int* in_sizes, int n_in,
                              void* d_out, int out_size) {
    const float* query = (const float*)d_in[0];
    const float* mem   = (const float*)d_in[1];
    const float* imp   = (const float*)d_in[2];
    const int*   ts    = (const int*)d_in[3];
    const float* Wq    = (const float*)d_in[4];
    const float* bqv   = (const float*)d_in[5];
    const int*   ct    = (const int*)d_in[6];

    int N = in_sizes[1] / DD;
    float* out = (float*)d_out;

    cudaFuncSetAttribute(k_main, cudaFuncAttributeMaxDynamicSharedMemorySize, SMEM_BYTES);
    cudaFuncSetAttribute(k_topk, cudaFuncAttributeMaxDynamicSharedMemorySize, TOPK_SMEM);

    int tiles = (N + TILE_R - 1) / TILE_R;
    int tpc = (tiles + NCTA - 1) / NCTA;
    k_main<<<NCTA, TPB, SMEM_BYTES>>>(query, mem, imp, ts, Wq, bqv, ct, N, tpc);
    k_topk<<<BQ, 256, TOPK_SMEM>>>(mem, imp, ts, ct, out);
    k_nov<<<BQ, 256>>>(out);
}

// round 16
// speedup vs baseline: 1.0402x; 1.0402x over previous
#include <cuda_runtime.h>
#include <cuda_bf16.h>
#include <math_constants.h>
#include <cstdint>

#define DD 128
#define BQ 32
#define KTOP 16
#define TILE_R 64
#define TPB 256
#define NCTA 444
#define SCST 34

// smem byte offsets (per CTA, ~46.7 KB -> 3 CTAs/SM)
#define SM_AHI  0              // 64 rows x 256B bf16 (16 KB); fp32 scratch in setup
#define SM_QHI  16384          // 32 rows x 256B bf16 (8 KB)
#define SM_SC   24576          // 64*34*4 = 8704
#define SM_NP   33280          // 64*33 floats = 8448 (norm partials)
#define SM_RW   41728          // 64 floats
#define SM_W    41984          // 64 floats
#define SM_CB   42240          // 32 floats
#define SM_TH   42368          // 32 floats
#define SM_FLG  42496          // 32 ints
#define SM_HV   42624          // 32*16 floats
#define SM_HX   44672          // 32*16 ints
#define SMEM_BYTES 46720

__device__ float g_q[BQ*DD];
__device__ float g_qn[BQ];
__device__ float g_cand_s[NCTA*BQ*KTOP];
__device__ int   g_cand_i[NCTA*BQ*KTOP];
__device__ float g_minred[NCTA*BQ];

// ---------------- helpers ----------------
__device__ __forceinline__ uint32_t smem_u32(const void* p) {
    uint32_t a;
    asm("{ .reg .u64 t; cvta.to.shared.u64 t, %1; cvt.u32.u64 %0, t; }" : "=r"(a) : "l"(p));
    return a;
}
__device__ __forceinline__ uint32_t pack_bf16x2(float hi_elem, float lo_elem) {
    uint32_t r;
    asm("cvt.rn.bf16x2.f32 %0, %1, %2;" : "=r"(r) : "f"(hi_elem), "f"(lo_elem));
    return r;
}
__device__ __forceinline__ float rsqrt_nr(float x) {
    float r;
    asm("rsqrt.approx.f32 %0, %1;" : "=f"(r) : "f"(x));
    r = r * fmaf(-0.5f * x * r, r, 1.5f);
    return r;
}
__device__ __forceinline__ void ldsm_x4(uint32_t& r0, uint32_t& r1, uint32_t& r2, uint32_t& r3, uint32_t a) {
    asm volatile("ldmatrix.sync.aligned.m8n8.x4.shared.b16 {%0,%1,%2,%3}, [%4];"
                 : "=r"(r0), "=r"(r1), "=r"(r2), "=r"(r3) : "r"(a));
}
__device__ __forceinline__ void ldsm_x2(uint32_t& r0, uint32_t& r1, uint32_t a) {
    asm volatile("ldmatrix.sync.aligned.m8n8.x2.shared.b16 {%0,%1}, [%2];"
                 : "=r"(r0), "=r"(r1) : "r"(a));
}
__device__ __forceinline__ void mma16816(float* c, uint32_t a0, uint32_t a1, uint32_t a2, uint32_t a3,
                                         uint32_t b0, uint32_t b1) {
    asm volatile("mma.sync.aligned.m16n8k16.row.col.f32.bf16.bf16.f32 "
                 "{%0,%1,%2,%3}, {%4,%5,%6,%7}, {%8,%9}, {%0,%1,%2,%3};"
                 : "+f"(c[0]), "+f"(c[1]), "+f"(c[2]), "+f"(c[3])
                 : "r"(a0), "r"(a1), "r"(a2), "r"(a3), "r"(b0), "r"(b1));
}

// ---------------------------------------------------------------------------
// k_main: pipelined register-staged bf16 HMMA dots (64-row tiles, 3 CTAs/SM)
// ---------------------------------------------------------------------------
__global__ void __launch_bounds__(TPB, 3)
k_main(const float* __restrict__ query, const float* __restrict__ mem,
       const float* __restrict__ imp, const int* __restrict__ ts,
       const float* __restrict__ Wq, const float* __restrict__ bqv,
       const int* __restrict__ ctp, int N, int tpc) {
    extern __shared__ char smem[];
    const uint32_t sb = smem_u32(smem);
    float* sSC  = (float*)(smem + SM_SC);
    float* sNP  = (float*)(smem + SM_NP);
    float* sRW  = (float*)(smem + SM_RW);
    float* sW   = (float*)(smem + SM_W);
    float* sCB  = (float*)(smem + SM_CB);
    float* sTH  = (float*)(smem + SM_TH);
    int*   sFLG = (int*)(smem + SM_FLG);
    float* sHV  = (float*)(smem + SM_HV);
    int*   sHX  = (int*)(smem + SM_HX);

    const int t    = threadIdx.x;
    const int wid  = t >> 5;
    const int lane = t & 31;
    const int cta  = blockIdx.x;

    // ===== setup: exact q = query @ Wq^T + bq; Qhi bf16 operand =====
    {
        float* sQF = (float*)(smem + SM_AHI);   // fp32 scratch (16 KB)
        for (int o = t; o < BQ*DD; o += TPB) {
            int b = o >> 7, j = o & 127;
            const float4* wr = (const float4*)(Wq + (size_t)j * DD);
            const float4* qr = (const float4*)(query + (size_t)b * DD);
            float a0 = 0.f, a1 = 0.f, a2 = 0.f, a3 = 0.f;
            #pragma unroll 8
            for (int dd = 0; dd < 32; dd++) {
                float4 wv = wr[dd]; float4 qv = qr[dd];
                a0 = fmaf(qv.x, wv.x, a0); a1 = fmaf(qv.y, wv.y, a1);
                a2 = fmaf(qv.z, wv.z, a2); a3 = fmaf(qv.w, wv.w, a3);
            }
            float v = ((a0 + a1) + (a2 + a3)) + bqv[j];
            sQF[o] = v;
            g_q[o] = v;
        }
        __syncthreads();
        if (t < BQ) {
            float s = 0.f;
            for (int jj = 0; jj < DD; jj++) {
                int j = (jj + 5*t) & 127;
                float v = sQF[t*DD + j];
                s = fmaf(v, v, s);
            }
            float qn = sqrtf(s);
            g_qn[t] = qn;
            sCB[t] = 0.7f / qn;
            sTH[t] = -CUDART_INF_F;
            sFLG[t] = 0;
        }
        for (int o = t; o < BQ*KTOP; o += TPB) { sHV[o] = -CUDART_INF_F; sHX[o] = 0x7fffffff; }
        __syncthreads();
        for (int o = t; o < BQ*DD; o += TPB) {
            int b = o >> 7, j = o & 127;
            *(__nv_bfloat16*)(smem + SM_QHI + b*256 + (((j >> 3) ^ (b & 7)) << 4) + (j & 7)*2)
                = __float2bfloat16(sQF[o]);
        }
        __syncthreads();   // QHI ready; AHI region free
    }

    const float inv_ct1 = 1.0f / ((float)(*ctp) + 1.0f);

    float lmn[4];
    #pragma unroll
    for (int j = 0; j < 4; j++) lmn[j] = CUDART_INF_F;

    const long tile0 = (long)cta * tpc;

    // assignments
    const int p    = wid & 3;            // mma slab id
    const int qhf  = wid >> 2;           // mma query half
    const int rsl  = p * 16;
    const int rA   = rsl + (lane & 15);
    const uint32_t aBase = sb + SM_AHI + rA * 256;
    const int aSel = lane >> 4;
    const int qB   = lane & 7;
    const int bSel = (lane >> 3) & 1;
    const int gid  = lane >> 2;
    const int tig  = lane & 3;
    const int r0l  = wid * 8;            // convert rows
    const uint32_t stoff = (uint32_t)((lane & 1) * 8);

    // ---- prologue: load tile 0 rows + scalars into registers ----
    float4 v[8];
    int   tsr  = 0;
    float impr = 0.f;
    {
        int base = (int)(tile0 * TILE_R);
        if (base < N) {
            const float4* g0 = (const float4*)(mem + (size_t)(base + r0l) * DD) + lane;
            if (base + TILE_R <= N) {
                #pragma unroll
                for (int j = 0; j < 8; j++) v[j] = g0[j * 32];
            } else {
                #pragma unroll
                for (int j = 0; j < 8; j++) {
                    v[j] = make_float4(0.f, 0.f, 0.f, 0.f);
                    if (base + r0l + j < N) v[j] = g0[j * 32];
                }
            }
            if (lane < 8) {
                int row = base + r0l + lane;
                if (row < N) { tsr = ts[row]; impr = imp[row]; }
            }
        }
    }

    for (int it = 0; it < tpc; it++) {
        int base = (int)((tile0 + it) * TILE_R);
        if (base >= N) break;

        // ---- convert: partials + bf16 + swizzled STS (v consumed here) ----
        #pragma unroll
        for (int j = 0; j < 8; j++) {
            int r = r0l + j;
            float s = v[j].x*v[j].x + v[j].y*v[j].y + v[j].z*v[j].z + v[j].w*v[j].w;
            sNP[r*33 + lane] = s;
            uint2 w2;
            w2.x = pack_bf16x2(v[j].y, v[j].x);
            w2.y = pack_bf16x2(v[j].w, v[j].z);
            uint32_t addr = sb + SM_AHI + (uint32_t)(r * 256)
                          + (uint32_t)((((lane >> 1) ^ (r & 7)) << 4)) + stoff;
            asm volatile("st.shared.v2.u32 [%0], {%1, %2};" :: "r"(addr), "r"(w2.x), "r"(w2.y) : "memory");
        }
        // per-row scalars from prefetched registers
        if (lane < 8) {
            int r = r0l + lane;
            sRW[r] = 0.3f * ((float)tsr + 1.0f) * inv_ct1;
            sW[r]  = fmaf(0.5f, impr, 0.5f);
        }

        // ---- issue NEXT tile loads (v dead; latency hides under mma) ----
        {
            int nbase = (int)((tile0 + it + 1) * TILE_R);
            if (it + 1 < tpc && nbase < N) {
                const float4* g0 = (const float4*)(mem + (size_t)(nbase + r0l) * DD) + lane;
                if (nbase + TILE_R <= N) {
                    #pragma unroll
                    for (int j = 0; j < 8; j++) v[j] = g0[j * 32];
                } else {
                    #pragma unroll
                    for (int j = 0; j < 8; j++) {
                        v[j] = make_float4(0.f, 0.f, 0.f, 0.f);
                        if (nbase + r0l + j < N) v[j] = g0[j * 32];
                    }
                }
                if (lane < 8) {
                    int row = nbase + r0l + lane;
                    tsr = 0; impr = 0.f;
                    if (row < N) { tsr = ts[row]; impr = imp[row]; }
                }
            }
        }
        __syncthreads();   // AHI + partials + scalars visible

        // ---- norm reduction: 16 conflict-free LDS + 3 shfl ----
        float mnA, mnB;
        {
            int rr = rsl + (lane & 15);
            const float* np = sNP + rr*33 + ((lane >> 4) << 4);
            float s = 0.f;
            #pragma unroll
            for (int j = 0; j < 16; j++) s += np[j];
            s += __shfl_xor_sync(0xffffffffu, s, 16);
            mnA = __shfl_sync(0xffffffffu, s, gid);
            mnB = __shfl_sync(0xffffffffu, s, gid + 8);
        }

        // ---- HMMA: 16-row slab x 16-query half, K=128 ----
        float C[2][4];
        #pragma unroll
        for (int nt = 0; nt < 2; nt++)
            #pragma unroll
            for (int i = 0; i < 4; i++) C[nt][i] = 0.f;

        const uint32_t qb0 = sb + SM_QHI + (qhf*16 + 0*8 + qB)*256;
        const uint32_t qb1 = sb + SM_QHI + (qhf*16 + 1*8 + qB)*256;
        #pragma unroll
        for (int ks = 0; ks < 8; ks++) {
            uint32_t a0, a1, a2, a3;
            ldsm_x4(a0, a1, a2, a3, aBase + (((2*ks + aSel) ^ (rA & 7)) << 4));
            uint32_t swz = ((2*ks + bSel) ^ qB) << 4;
            uint32_t b0, b1;
            ldsm_x2(b0, b1, qb0 + swz); mma16816(C[0], a0, a1, a2, a3, b0, b1);
            ldsm_x2(b0, b1, qb1 + swz); mma16816(C[1], a0, a1, a2, a3, b0, b1);
        }

        // ---- epilogue: scores + min-d2 + direct flags ----
        {
            int rla = rsl + gid, rlb = rla + 8;
            bool va = (base + rla < N), vb = (base + rlb < N);
            float invA = va ? rsqrt_nr(mnA) : 0.f;
            float invB = vb ? rsqrt_nr(mnB) : 0.f;
            float recA = sRW[rla], wA = sW[rla];
            float recB = sRW[rlb], wB = sW[rlb];
            #pragma unroll
            for (int nt = 0; nt < 2; nt++) {
                int q0 = qhf*16 + nt*8 + tig*2;
                float cb0 = sCB[q0], cb1 = sCB[q0+1];
                float dA0 = C[nt][0], dA1 = C[nt][1];
                float dB0 = C[nt][2], dB1 = C[nt][3];
                float2 sa, sbv;
                sa.x  = va ? fmaf(dA0*invA, cb0, recA) * wA : -CUDART_INF_F;
                sa.y  = va ? fmaf(dA1*invA, cb1, recA) * wA : -CUDART_INF_F;
                sbv.x = vb ? fmaf(dB0*invB, cb0, recB) * wB : -CUDART_INF_F;
                sbv.y = vb ? fmaf(dB1*invB, cb1, recB) * wB : -CUDART_INF_F;
                *(float2*)(sSC + rla*SCST + q0) = sa;
                *(float2*)(sSC + rlb*SCST + q0) = sbv;
                float m0 = CUDART_INF_F, m1 = CUDART_INF_F;
                if (va) { m0 = fmaf(-2.f, dA0, mnA); m1 = fmaf(-2.f, dA1, mnA); }
                if (vb) { m0 = fminf(m0, fmaf(-2.f, dB0, mnB)); m1 = fminf(m1, fmaf(-2.f, dB1, mnB)); }
                lmn[nt*2]   = fminf(lmn[nt*2],   m0);
                lmn[nt*2+1] = fminf(lmn[nt*2+1], m1);
                // direct threshold test (idempotent flag store; rarely taken)
                float th0 = sTH[q0], th1 = sTH[q0+1];
                if (fmaxf(sa.x, sbv.x) > th0) sFLG[q0]   = 1;
                if (fmaxf(sa.y, sbv.y) > th1) sFLG[q0+1] = 1;
            }
        }
        __syncthreads();

        // ---- phase B: full 64-row scan only when flagged ----
        if (t < BQ && sFLG[t]) {
            sFLG[t] = 0;
            float th = sTH[t];
            float* hv = sHV + t*KTOP;
            int*   hx = sHX + t*KTOP;
            for (int e = 0; e < TILE_R; e += 4) {
                float v0 = sSC[(e+0)*SCST + t];
                float v1 = sSC[(e+1)*SCST + t];
                float v2 = sSC[(e+2)*SCST + t];
                float v3 = sSC[(e+3)*SCST + t];
                float mx = fmaxf(fmaxf(v0, v1), fmaxf(v2, v3));
                if (mx > th) {
                    #pragma unroll
                    for (int u = 0; u < 4; u++) {
                        float sc = (u==0)?v0:(u==1)?v1:(u==2)?v2:v3;
                        if (sc > th) {
                            int idx = base + e + u;
                            int pos = KTOP - 1;
                            #pragma unroll
                            for (int s = KTOP - 1; s > 0; s--)
                                if (sc > hv[s-1]) { hv[s] = hv[s-1]; hx[s] = hx[s-1]; pos = s-1; }
                            hv[pos] = sc; hx[pos] = idx;
                            th = hv[KTOP-1];
                        }
                    }
                }
            }
            sTH[t] = th;
        }
        // no barrier: next iter's pre-MMA __syncthreads orders phase B vs sSC reuse
    }
    __syncthreads();

    // ---- reduce lmn: q = qhf*16 + nt*8 + tig*2 + pp; 32 contributors/q ----
    #pragma unroll
    for (int nt = 0; nt < 2; nt++)
        #pragma unroll
        for (int pp = 0; pp < 2; pp++) {
            int q = qhf*16 + nt*8 + tig*2 + pp;
            sSC[q*32 + p*8 + gid] = lmn[nt*2+pp];
        }
    __syncthreads();
    if (t < BQ) {
        float mn = CUDART_INF_F;
        #pragma unroll 4
        for (int i = 0; i < 32; i++) mn = fminf(mn, sSC[t*32 + ((i + t) & 31)]);
        g_minred[cta*BQ + t] = mn;
        float* cs = g_cand_s + ((size_t)cta*BQ + t) * KTOP;
        int*   ci = g_cand_i + ((size_t)cta*BQ + t) * KTOP;
        #pragma unroll
        for (int j = 0; j < KTOP; j++) { cs[j] = sHV[t*KTOP + j]; ci[j] = sHX[t*KTOP + j]; }
    }
}

// ---------------------------------------------------------------------------
// k_topk: approx top-32 merge (dynamic smem), exact rescoring, exact top-16
// ---------------------------------------------------------------------------
#define MCAND (NCTA*KTOP)
#define TOPK_SMEM (MCAND*8)
__global__ void __launch_bounds__(256)
k_topk(const float* __restrict__ mem, const float* __restrict__ imp,
       const int* __restrict__ ts, const int* __restrict__ ctp,
       float* __restrict__ out) {
    extern __shared__ char dyn[];
    float* cs = (float*)dyn;
    int*   ci = (int*)(dyn + MCAND*4);
    __shared__ float rv[256];
    __shared__ int   ri[256], rp[256];
    __shared__ int   candI[32];
    __shared__ float exS[32];
    __shared__ int   exI[32];

    int q = blockIdx.x;
    int t = threadIdx.x;

    for (int i = t; i < MCAND; i += 256) {
        int c = i >> 4, j = i & (KTOP-1);
        size_t g = ((size_t)c*BQ + q) * KTOP + j;
        cs[i] = g_cand_s[g];
        ci[i] = g_cand_i[g];
    }
    __syncthreads();

    for (int pass = 0; pass < 32; pass++) {
        float bv = -CUDART_INF_F; int bi = 0x7fffffff, bp = 0;
        for (int i = t; i < MCAND; i += 256) {
            float v = cs[i]; int id = ci[i];
            if (v > bv || (v == bv && id < bi)) { bv = v; bi = id; bp = i; }
        }
        rv[t] = bv; ri[t] = bi; rp[t] = bp;
        __syncthreads();
        for (int s = 128; s > 0; s >>= 1) {
            if (t < s && (rv[t+s] > rv[t] || (rv[t+s] == rv[t] && ri[t+s] < ri[t]))) {
                rv[t] = rv[t+s]; ri[t] = ri[t+s]; rp[t] = rp[t+s];
            }
            __syncthreads();
        }
        if (t == 0) {
            candI[pass] = (rv[0] == -CUDART_INF_F) ? 0x7fffffff : ri[0];
            cs[rp[0]] = -CUDART_INF_F;
        }
        __syncthreads();
    }

    const float ctf1 = (float)(*ctp) + 1.0f;
    if (t < 32) {
        int idx = candI[t];
        float sc = -CUDART_INF_F;
        if (idx != 0x7fffffff) {
            const float4* mr = (const float4*)(mem + (size_t)idx * DD);
            const float4* qr = (const float4*)(g_q + q * DD);
            float dot = 0.f, mn2 = 0.f;
            #pragma unroll 8
            for (int c = 0; c < 32; c++) {
                float4 a = mr[c]; float4 b = qr[c];
                dot = fmaf(a.x, b.x, dot); dot = fmaf(a.y, b.y, dot);
                dot = fmaf(a.z, b.z, dot); dot = fmaf(a.w, b.w, dot);
                mn2 = fmaf(a.x, a.x, mn2); mn2 = fmaf(a.y, a.y, mn2);
                mn2 = fmaf(a.z, a.z, mn2); mn2 = fmaf(a.w, a.w, mn2);
            }
            float den = fmaxf(g_qn[q] * sqrtf(mn2), 1e-8f);
            float rec = ((float)ts[idx] + 1.0f) / ctf1;
            sc = (0.7f * dot / den + 0.3f * rec) * fmaf(0.5f, imp[idx], 0.5f);
        }
        exS[t] = sc; exI[t] = idx;
    }
    __syncthreads();

    if (t == 0) {
        for (int pass = 0; pass < KTOP; pass++) {
            float bv = -CUDART_INF_F; int bi = 0x7fffffff, bp = 0;
            for (int i = 0; i < 32; i++)
                if (exS[i] > bv || (exS[i] == bv && exI[i] < bi)) { bv = exS[i]; bi = exI[i]; bp = i; }
            out[q*KTOP + pass]           = bv;
            out[BQ*KTOP + q*KTOP + pass] = (float)bi;
            exS[bp] = -CUDART_INF_F;
        }
    }
}

// ---------------------------------------------------------------------------
__global__ void __launch_bounds__(256)
k_nov(float* __restrict__ out) {
    __shared__ float rv[256];
    int q = blockIdx.x, t = threadIdx.x;
    float m = CUDART_INF_F;
    for (int c = t; c < NCTA; c += 256) m = fminf(m, g_minred[c*BQ + q]);
    rv[t] = m;
    __syncthreads();
    for (int s = 128; s > 0; s >>= 1) {
        if (t < s) rv[t] = fminf(rv[t], rv[t+s]);
        __syncthreads();
    }
    if (t == 0) {
        float qn = g_qn[q];
        float dist = sqrtf(fmaxf(qn*qn + rv[0], 0.0f));
        out[2*BQ*KTOP + q] = fminf(1.0f, dist * 0.1f);
    }
}

// ---------------------------------------------------------------------------
extern "C" void kernel_launch(void* const* d_in, const int* in_sizes, int n_in,
                              void* d_out, int out_size) {
    const float* query = (const float*)d_in[0];
    const float* mem   = (const float*)d_in[1];
    const float* imp   = (const float*)d_in[2];
    const int*   ts    = (const int*)d_in[3];
    const float* Wq    = (const float*)d_in[4];
    const float* bqv   = (const float*)d_in[5];
    const int*   ct    = (const int*)d_in[6];

    int N = in_sizes[1] / DD;
    float* out = (float*)d_out;

    cudaFuncSetAttribute(k_main, cudaFuncAttributeMaxDynamicSharedMemorySize, SMEM_BYTES);
    cudaFuncSetAttribute(k_topk, cudaFuncAttributeMaxDynamicSharedMemorySize, TOPK_SMEM);

    int tiles = (N + TILE_R - 1) / TILE_R;
    int tpc = (tiles + NCTA - 1) / NCTA;
    k_main<<<NCTA, TPB, SMEM_BYTES>>>(query, mem, imp, ts, Wq, bqv, ct, N, tpc);
    k_topk<<<BQ, 256, TOPK_SMEM>>>(mem, imp, ts, ct, out);
    k_nov<<<BQ, 256>>>(out);
}

// round 17
// speedup vs baseline: 1.1415x; 1.0974x over previous
#include <cuda_runtime.h>
#include <cuda_bf16.h>
#include <math_constants.h>
#include <cstdint>

#define DD 128
#define BQ 32
#define KTOP 16
#define TILE_R 64
#define TPB 256
#define NCTA 296
#define SCST 34

// smem byte offsets (per CTA, ~46.7 KB -> 2 CTAs/SM)
#define SM_AHI  0              // 64 rows x 256B bf16 (16 KB); fp32 scratch in setup
#define SM_QHI  16384          // 32 rows x 256B bf16 (8 KB)
#define SM_SC   24576          // 64*34*4 = 8704
#define SM_NP   33280          // 64*33 floats = 8448 (norm partials)
#define SM_RW   41728          // 64 floats
#define SM_W    41984          // 64 floats
#define SM_CB   42240          // 32 floats
#define SM_TH   42368          // 32 floats
#define SM_FLG  42496          // 32 ints
#define SM_HV   42624          // 32*16 floats
#define SM_HX   44672          // 32*16 ints
#define SMEM_BYTES 46720

__device__ float g_q[BQ*DD];
__device__ float g_qn[BQ];
__device__ float g_cand_s[NCTA*BQ*KTOP];
__device__ int   g_cand_i[NCTA*BQ*KTOP];
__device__ float g_minred[NCTA*BQ];

// ---------------- helpers ----------------
__device__ __forceinline__ uint32_t smem_u32(const void* p) {
    uint32_t a;
    asm("{ .reg .u64 t; cvta.to.shared.u64 t, %1; cvt.u32.u64 %0, t; }" : "=r"(a) : "l"(p));
    return a;
}
__device__ __forceinline__ uint32_t pack_bf16x2(float hi_elem, float lo_elem) {
    uint32_t r;
    asm("cvt.rn.bf16x2.f32 %0, %1, %2;" : "=r"(r) : "f"(hi_elem), "f"(lo_elem));
    return r;
}
__device__ __forceinline__ float rsqrt_nr(float x) {
    float r;
    asm("rsqrt.approx.f32 %0, %1;" : "=f"(r) : "f"(x));
    r = r * fmaf(-0.5f * x * r, r, 1.5f);
    return r;
}
__device__ __forceinline__ void ldsm_x4(uint32_t& r0, uint32_t& r1, uint32_t& r2, uint32_t& r3, uint32_t a) {
    asm volatile("ldmatrix.sync.aligned.m8n8.x4.shared.b16 {%0,%1,%2,%3}, [%4];"
                 : "=r"(r0), "=r"(r1), "=r"(r2), "=r"(r3) : "r"(a));
}
__device__ __forceinline__ void ldsm_x2(uint32_t& r0, uint32_t& r1, uint32_t a) {
    asm volatile("ldmatrix.sync.aligned.m8n8.x2.shared.b16 {%0,%1}, [%2];"
                 : "=r"(r0), "=r"(r1) : "r"(a));
}
__device__ __forceinline__ void mma16816(float* c, uint32_t a0, uint32_t a1, uint32_t a2, uint32_t a3,
                                         uint32_t b0, uint32_t b1) {
    asm volatile("mma.sync.aligned.m16n8k16.row.col.f32.bf16.bf16.f32 "
                 "{%0,%1,%2,%3}, {%4,%5,%6,%7}, {%8,%9}, {%0,%1,%2,%3};"
                 : "+f"(c[0]), "+f"(c[1]), "+f"(c[2]), "+f"(c[3])
                 : "r"(a0), "r"(a1), "r"(a2), "r"(a3), "r"(b0), "r"(b1));
}

// ---------------------------------------------------------------------------
// k_main: pipelined register-staged bf16 HMMA dots, Q-fragments in registers
// ---------------------------------------------------------------------------
__global__ void __launch_bounds__(TPB, 2)
k_main(const float* __restrict__ query, const float* __restrict__ mem,
       const float* __restrict__ imp, const int* __restrict__ ts,
       const float* __restrict__ Wq, const float* __restrict__ bqv,
       const int* __restrict__ ctp, int N, int tpc) {
    extern __shared__ char smem[];
    const uint32_t sb = smem_u32(smem);
    float* sSC  = (float*)(smem + SM_SC);
    float* sNP  = (float*)(smem + SM_NP);
    float* sRW  = (float*)(smem + SM_RW);
    float* sW   = (float*)(smem + SM_W);
    float* sCB  = (float*)(smem + SM_CB);
    float* sTH  = (float*)(smem + SM_TH);
    int*   sFLG = (int*)(smem + SM_FLG);
    float* sHV  = (float*)(smem + SM_HV);
    int*   sHX  = (int*)(smem + SM_HX);

    const int t    = threadIdx.x;
    const int wid  = t >> 5;
    const int lane = t & 31;
    const int cta  = blockIdx.x;

    // ===== setup: exact q = query @ Wq^T + bq; Qhi bf16 operand =====
    {
        float* sQF = (float*)(smem + SM_AHI);   // fp32 scratch (16 KB)
        for (int o = t; o < BQ*DD; o += TPB) {
            int b = o >> 7, j = o & 127;
            const float4* wr = (const float4*)(Wq + (size_t)j * DD);
            const float4* qr = (const float4*)(query + (size_t)b * DD);
            float a0 = 0.f, a1 = 0.f, a2 = 0.f, a3 = 0.f;
            #pragma unroll 8
            for (int dd = 0; dd < 32; dd++) {
                float4 wv = wr[dd]; float4 qv = qr[dd];
                a0 = fmaf(qv.x, wv.x, a0); a1 = fmaf(qv.y, wv.y, a1);
                a2 = fmaf(qv.z, wv.z, a2); a3 = fmaf(qv.w, wv.w, a3);
            }
            float v = ((a0 + a1) + (a2 + a3)) + bqv[j];
            sQF[o] = v;
            g_q[o] = v;
        }
        __syncthreads();
        if (t < BQ) {
            float s = 0.f;
            for (int jj = 0; jj < DD; jj++) {
                int j = (jj + 5*t) & 127;
                float v = sQF[t*DD + j];
                s = fmaf(v, v, s);
            }
            float qn = sqrtf(s);
            g_qn[t] = qn;
            sCB[t] = 0.7f / qn;
            sTH[t] = -CUDART_INF_F;
            sFLG[t] = 0;
        }
        for (int o = t; o < BQ*KTOP; o += TPB) { sHV[o] = -CUDART_INF_F; sHX[o] = 0x7fffffff; }
        __syncthreads();
        for (int o = t; o < BQ*DD; o += TPB) {
            int b = o >> 7, j = o & 127;
            *(__nv_bfloat16*)(smem + SM_QHI + b*256 + (((j >> 3) ^ (b & 7)) << 4) + (j & 7)*2)
                = __float2bfloat16(sQF[o]);
        }
        __syncthreads();   // QHI ready; AHI region free
    }

    const float inv_ct1 = 1.0f / ((float)(*ctp) + 1.0f);

    float lmn[4];
    #pragma unroll
    for (int j = 0; j < 4; j++) lmn[j] = CUDART_INF_F;

    const long tile0 = (long)cta * tpc;

    // assignments
    const int p    = wid & 3;            // mma slab id
    const int qhf  = wid >> 2;           // mma query half
    const int rsl  = p * 16;
    const int rA   = rsl + (lane & 15);
    const uint32_t aBase = sb + SM_AHI + rA * 256;
    const int aSel = lane >> 4;
    const int qB   = lane & 7;
    const int bSel = (lane >> 3) & 1;
    const int gid  = lane >> 2;
    const int tig  = lane & 3;
    const int r0l  = wid * 8;            // convert rows
    const uint32_t stoff = (uint32_t)((lane & 1) * 8);

    // ---- hoist Q fragments into registers (constant across all tiles) ----
    uint32_t qf[8][2][2];
    {
        const uint32_t qb0 = sb + SM_QHI + (qhf*16 + 0*8 + qB)*256;
        const uint32_t qb1 = sb + SM_QHI + (qhf*16 + 1*8 + qB)*256;
        #pragma unroll
        for (int ks = 0; ks < 8; ks++) {
            uint32_t swz = ((2*ks + bSel) ^ qB) << 4;
            ldsm_x2(qf[ks][0][0], qf[ks][0][1], qb0 + swz);
            ldsm_x2(qf[ks][1][0], qf[ks][1][1], qb1 + swz);
        }
    }

    // ---- prologue: load tile 0 rows + scalars into registers ----
    float4 v[8];
    int   tsr  = 0;
    float impr = 0.f;
    {
        int base = (int)(tile0 * TILE_R);
        if (base < N) {
            const float4* g0 = (const float4*)(mem + (size_t)(base + r0l) * DD) + lane;
            if (base + TILE_R <= N) {
                #pragma unroll
                for (int j = 0; j < 8; j++) v[j] = g0[j * 32];
            } else {
                #pragma unroll
                for (int j = 0; j < 8; j++) {
                    v[j] = make_float4(0.f, 0.f, 0.f, 0.f);
                    if (base + r0l + j < N) v[j] = g0[j * 32];
                }
            }
            if (lane < 8) {
                int row = base + r0l + lane;
                if (row < N) { tsr = ts[row]; impr = imp[row]; }
            }
        }
    }

    for (int it = 0; it < tpc; it++) {
        int base = (int)((tile0 + it) * TILE_R);
        if (base >= N) break;

        // ---- convert: partials + bf16 + swizzled STS (v consumed here) ----
        #pragma unroll
        for (int j = 0; j < 8; j++) {
            int r = r0l + j;
            float s = v[j].x*v[j].x + v[j].y*v[j].y + v[j].z*v[j].z + v[j].w*v[j].w;
            sNP[r*33 + lane] = s;
            uint2 w2;
            w2.x = pack_bf16x2(v[j].y, v[j].x);
            w2.y = pack_bf16x2(v[j].w, v[j].z);
            uint32_t addr = sb + SM_AHI + (uint32_t)(r * 256)
                          + (uint32_t)((((lane >> 1) ^ (r & 7)) << 4)) + stoff;
            asm volatile("st.shared.v2.u32 [%0], {%1, %2};" :: "r"(addr), "r"(w2.x), "r"(w2.y) : "memory");
        }
        // per-row scalars from prefetched registers
        if (lane < 8) {
            int r = r0l + lane;
            sRW[r] = 0.3f * ((float)tsr + 1.0f) * inv_ct1;
            sW[r]  = fmaf(0.5f, impr, 0.5f);
        }

        // ---- issue NEXT tile loads (v dead; latency hides under mma) ----
        {
            int nbase = (int)((tile0 + it + 1) * TILE_R);
            if (it + 1 < tpc && nbase < N) {
                const float4* g0 = (const float4*)(mem + (size_t)(nbase + r0l) * DD) + lane;
                if (nbase + TILE_R <= N) {
                    #pragma unroll
                    for (int j = 0; j < 8; j++) v[j] = g0[j * 32];
                } else {
                    #pragma unroll
                    for (int j = 0; j < 8; j++) {
                        v[j] = make_float4(0.f, 0.f, 0.f, 0.f);
                        if (nbase + r0l + j < N) v[j] = g0[j * 32];
                    }
                }
                if (lane < 8) {
                    int row = nbase + r0l + lane;
                    tsr = 0; impr = 0.f;
                    if (row < N) { tsr = ts[row]; impr = imp[row]; }
                }
            }
        }
        __syncthreads();   // AHI + partials + scalars visible

        // ---- norm reduction: 16 conflict-free LDS + 3 shfl ----
        float mnA, mnB;
        {
            int rr = rsl + (lane & 15);
            const float* np = sNP + rr*33 + ((lane >> 4) << 4);
            float s = 0.f;
            #pragma unroll
            for (int j = 0; j < 16; j++) s += np[j];
            s += __shfl_xor_sync(0xffffffffu, s, 16);
            mnA = __shfl_sync(0xffffffffu, s, gid);
            mnB = __shfl_sync(0xffffffffu, s, gid + 8);
        }

        // ---- HMMA: 16-row slab x 16-query half, K=128 (Q from registers) ----
        float C[2][4];
        #pragma unroll
        for (int nt = 0; nt < 2; nt++)
            #pragma unroll
            for (int i = 0; i < 4; i++) C[nt][i] = 0.f;

        #pragma unroll
        for (int ks = 0; ks < 8; ks++) {
            uint32_t a0, a1, a2, a3;
            ldsm_x4(a0, a1, a2, a3, aBase + (((2*ks + aSel) ^ (rA & 7)) << 4));
            mma16816(C[0], a0, a1, a2, a3, qf[ks][0][0], qf[ks][0][1]);
            mma16816(C[1], a0, a1, a2, a3, qf[ks][1][0], qf[ks][1][1]);
        }

        // ---- epilogue: scores + min-d2 + direct flags ----
        {
            int rla = rsl + gid, rlb = rla + 8;
            bool va = (base + rla < N), vb = (base + rlb < N);
            float invA = va ? rsqrt_nr(mnA) : 0.f;
            float invB = vb ? rsqrt_nr(mnB) : 0.f;
            float recA = sRW[rla], wA = sW[rla];
            float recB = sRW[rlb], wB = sW[rlb];
            #pragma unroll
            for (int nt = 0; nt < 2; nt++) {
                int q0 = qhf*16 + nt*8 + tig*2;
                float cb0 = sCB[q0], cb1 = sCB[q0+1];
                float dA0 = C[nt][0], dA1 = C[nt][1];
                float dB0 = C[nt][2], dB1 = C[nt][3];
                float2 sa, sbv;
                sa.x  = va ? fmaf(dA0*invA, cb0, recA) * wA : -CUDART_INF_F;
                sa.y  = va ? fmaf(dA1*invA, cb1, recA) * wA : -CUDART_INF_F;
                sbv.x = vb ? fmaf(dB0*invB, cb0, recB) * wB : -CUDART_INF_F;
                sbv.y = vb ? fmaf(dB1*invB, cb1, recB) * wB : -CUDART_INF_F;
                *(float2*)(sSC + rla*SCST + q0) = sa;
                *(float2*)(sSC + rlb*SCST + q0) = sbv;
                float m0 = CUDART_INF_F, m1 = CUDART_INF_F;
                if (va) { m0 = fmaf(-2.f, dA0, mnA); m1 = fmaf(-2.f, dA1, mnA); }
                if (vb) { m0 = fminf(m0, fmaf(-2.f, dB0, mnB)); m1 = fminf(m1, fmaf(-2.f, dB1, mnB)); }
                lmn[nt*2]   = fminf(lmn[nt*2],   m0);
                lmn[nt*2+1] = fminf(lmn[nt*2+1], m1);
                float th0 = sTH[q0], th1 = sTH[q0+1];
                if (fmaxf(sa.x, sbv.x) > th0) sFLG[q0]   = 1;
                if (fmaxf(sa.y, sbv.y) > th1) sFLG[q0+1] = 1;
            }
        }
        __syncthreads();

        // ---- phase B: full 64-row scan only when flagged ----
        if (t < BQ && sFLG[t]) {
            sFLG[t] = 0;
            float th = sTH[t];
            float* hv = sHV + t*KTOP;
            int*   hx = sHX + t*KTOP;
            for (int e = 0; e < TILE_R; e += 4) {
                float v0 = sSC[(e+0)*SCST + t];
                float v1 = sSC[(e+1)*SCST + t];
                float v2 = sSC[(e+2)*SCST + t];
                float v3 = sSC[(e+3)*SCST + t];
                float mx = fmaxf(fmaxf(v0, v1), fmaxf(v2, v3));
                if (mx > th) {
                    #pragma unroll
                    for (int u = 0; u < 4; u++) {
                        float sc = (u==0)?v0:(u==1)?v1:(u==2)?v2:v3;
                        if (sc > th) {
                            int idx = base + e + u;
                            int pos = KTOP - 1;
                            #pragma unroll
                            for (int s = KTOP - 1; s > 0; s--)
                                if (sc > hv[s-1]) { hv[s] = hv[s-1]; hx[s] = hx[s-1]; pos = s-1; }
                            hv[pos] = sc; hx[pos] = idx;
                            th = hv[KTOP-1];
                        }
                    }
                }
            }
            sTH[t] = th;
        }
        // no barrier: next iter's pre-MMA __syncthreads orders phase B vs sSC reuse
    }
    __syncthreads();

    // ---- reduce lmn: q = qhf*16 + nt*8 + tig*2 + pp; 32 contributors/q ----
    #pragma unroll
    for (int nt = 0; nt < 2; nt++)
        #pragma unroll
        for (int pp = 0; pp < 2; pp++) {
            int q = qhf*16 + nt*8 + tig*2 + pp;
            sSC[q*32 + p*8 + gid] = lmn[nt*2+pp];
        }
    __syncthreads();
    if (t < BQ) {
        float mn = CUDART_INF_F;
        #pragma unroll 4
        for (int i = 0; i < 32; i++) mn = fminf(mn, sSC[t*32 + ((i + t) & 31)]);
        g_minred[cta*BQ + t] = mn;
        float* cs = g_cand_s + ((size_t)cta*BQ + t) * KTOP;
        int*   ci = g_cand_i + ((size_t)cta*BQ + t) * KTOP;
        #pragma unroll
        for (int j = 0; j < KTOP; j++) { cs[j] = sHV[t*KTOP + j]; ci[j] = sHX[t*KTOP + j]; }
    }
}

// ---------------------------------------------------------------------------
// k_topk: approx top-32 merge (dynamic smem), exact rescoring, exact top-16
// ---------------------------------------------------------------------------
#define MCAND (NCTA*KTOP)
#define TOPK_SMEM (MCAND*8)
__global__ void __launch_bounds__(256)
k_topk(const float* __restrict__ mem, const float* __restrict__ imp,
       const int* __restrict__ ts, const int* __restrict__ ctp,
       float* __restrict__ out) {
    extern __shared__ char dyn[];
    float* cs = (float*)dyn;
    int*   ci = (int*)(dyn + MCAND*4);
    __shared__ float rv[256];
    __shared__ int   ri[256], rp[256];
    __shared__ int   candI[32];
    __shared__ float exS[32];
    __shared__ int   exI[32];

    int q = blockIdx.x;
    int t = threadIdx.x;

    for (int i = t; i < MCAND; i += 256) {
        int c = i >> 4, j = i & (KTOP-1);
        size_t g = ((size_t)c*BQ + q) * KTOP + j;
        cs[i] = g_cand_s[g];
        ci[i] = g_cand_i[g];
    }
    __syncthreads();

    for (int pass = 0; pass < 32; pass++) {
        float bv = -CUDART_INF_F; int bi = 0x7fffffff, bp = 0;
        for (int i = t; i < MCAND; i += 256) {
            float v = cs[i]; int id = ci[i];
            if (v > bv || (v == bv && id < bi)) { bv = v; bi = id; bp = i; }
        }
        rv[t] = bv; ri[t] = bi; rp[t] = bp;
        __syncthreads();
        for (int s = 128; s > 0; s >>= 1) {
            if (t < s && (rv[t+s] > rv[t] || (rv[t+s] == rv[t] && ri[t+s] < ri[t]))) {
                rv[t] = rv[t+s]; ri[t] = ri[t+s]; rp[t] = rp[t+s];
            }
            __syncthreads();
        }
        if (t == 0) {
            candI[pass] = (rv[0] == -CUDART_INF_F) ? 0x7fffffff : ri[0];
            cs[rp[0]] = -CUDART_INF_F;
        }
        __syncthreads();
    }

    const float ctf1 = (float)(*ctp) + 1.0f;
    if (t < 32) {
        int idx = candI[t];
        float sc = -CUDART_INF_F;
        if (idx != 0x7fffffff) {
            const float4* mr = (const float4*)(mem + (size_t)idx * DD);
            const float4* qr = (const float4*)(g_q + q * DD);
            float dot = 0.f, mn2 = 0.f;
            #pragma unroll 8
            for (int c = 0; c < 32; c++) {
                float4 a = mr[c]; float4 b = qr[c];
                dot = fmaf(a.x, b.x, dot); dot = fmaf(a.y, b.y, dot);
                dot = fmaf(a.z, b.z, dot); dot = fmaf(a.w, b.w, dot);
                mn2 = fmaf(a.x, a.x, mn2); mn2 = fmaf(a.y, a.y, mn2);
                mn2 = fmaf(a.z, a.z, mn2); mn2 = fmaf(a.w, a.w, mn2);
            }
            float den = fmaxf(g_qn[q] * sqrtf(mn2), 1e-8f);
            float rec = ((float)ts[idx] + 1.0f) / ctf1;
            sc = (0.7f * dot / den + 0.3f * rec) * fmaf(0.5f, imp[idx], 0.5f);
        }
        exS[t] = sc; exI[t] = idx;
    }
    __syncthreads();

    if (t == 0) {
        for (int pass = 0; pass < KTOP; pass++) {
            float bv = -CUDART_INF_F; int bi = 0x7fffffff, bp = 0;
            for (int i = 0; i < 32; i++)
                if (exS[i] > bv || (exS[i] == bv && exI[i] < bi)) { bv = exS[i]; bi = exI[i]; bp = i; }
            out[q*KTOP + pass]           = bv;
            out[BQ*KTOP + q*KTOP + pass] = (float)bi;
            exS[bp] = -CUDART_INF_F;
        }
    }
}

// ---------------------------------------------------------------------------
__global__ void __launch_bounds__(256)
k_nov(float* __restrict__ out) {
    __shared__ float rv[256];
    int q = blockIdx.x, t = threadIdx.x;
    float m = CUDART_INF_F;
    for (int c = t; c < NCTA; c += 256) m = fminf(m, g_minred[c*BQ + q]);
    rv[t] = m;
    __syncthreads();
    for (int s = 128; s > 0; s >>= 1) {
        if (t < s) rv[t] = fminf(rv[t], rv[t+s]);
        __syncthreads();
    }
    if (t == 0) {
        float qn = g_qn[q];
        float dist = sqrtf(fmaxf(qn*qn + rv[0], 0.0f));
        out[2*BQ*KTOP + q] = fminf(1.0f, dist * 0.1f);
    }
}

// ---------------------------------------------------------------------------
extern "C" void kernel_launch(void* const* d_in, const int* in_sizes, int n_in,
                              void* d_out, int out_size) {
    const float* query = (const float*)d_in[0];
    const float* mem   = (const float*)d_in[1];
    const float* imp   = (const float*)d_in[2];
    const int*   ts    = (const int*)d_in[3];
    const float* Wq    = (const float*)d_in[4];
    const float* bqv   = (const float*)d_in[5];
    const int*   ct    = (const int*)d_in[6];

    int N = in_sizes[1] / DD;
    float* out = (float*)d_out;

    cudaFuncSetAttribute(k_main, cudaFuncAttributeMaxDynamicSharedMemorySize, SMEM_BYTES);
    cudaFuncSetAttribute(k_topk, cudaFuncAttributeMaxDynamicSharedMemorySize, TOPK_SMEM);

    int tiles = (N + TILE_R - 1) / TILE_R;
    int tpc = (tiles + NCTA - 1) / NCTA;
    k_main<<<NCTA, TPB, SMEM_BYTES>>>(query, mem, imp, ts, Wq, bqv, ct, N, tpc);
    k_topk<<<BQ, 256, TOPK_SMEM>>>(mem, imp, ts, ct, out);
    k_nov<<<BQ, 256>>>(out);
}